// round 1
// baseline (speedup 1.0000x reference)
#include <cuda_runtime.h>
#include <math.h>

// Problem shape (fixed by the dataset)
#define NB   16
#define SEQ  2048
#define DH   256
#define BQ   64     // q rows per CTA
#define BK   64     // kv rows per tile
#define QS   260    // smem row stride (floats) for Q/K/V tiles: (r*260+c)%32 = (4r+c)%32 -> conflict-free frags
#define PSS  68     // smem row stride for P tile
#define NEGINF (-INFINITY)

__device__ __forceinline__ unsigned f2tf(float f) {
    unsigned r;
    asm("cvt.rna.tf32.f32 %0, %1;" : "=r"(r) : "f"(f));
    return r;
}

// D += A(16x8 tf32, row) * B(8x8 tf32, col)
__device__ __forceinline__ void mma8(float* d, const unsigned* a, const unsigned* b) {
    asm volatile(
        "mma.sync.aligned.m16n8k8.row.col.f32.tf32.tf32.f32 "
        "{%0,%1,%2,%3}, {%4,%5,%6,%7}, {%8,%9}, {%0,%1,%2,%3};"
        : "+f"(d[0]), "+f"(d[1]), "+f"(d[2]), "+f"(d[3])
        : "r"(a[0]), "r"(a[1]), "r"(a[2]), "r"(a[3]),
          "r"(b[0]), "r"(b[1]));
}

__global__ void __launch_bounds__(128, 1) attn_kernel(
    const float* __restrict__ Qg, const float* __restrict__ Kg,
    const float* __restrict__ Vg, const int* __restrict__ Mg,
    float* __restrict__ Og)
{
    extern __shared__ float smf[];
    float* Qs = smf;                 // BQ x QS
    float* Ks = Qs + BQ * QS;        // BK x QS
    float* Vs = Ks + BK * QS;        // BK x QS
    float* Ps = Vs + BK * QS;        // BQ x PSS
    int*   Ms = (int*)(Ps + BQ * PSS); // BK ints

    // Heavy (large qt) blocks first to pack the causal-imbalance tail.
    const int qt  = gridDim.x - 1 - blockIdx.x;
    const int b   = blockIdx.y;
    const int tid = threadIdx.x;
    const int wid = tid >> 5;
    const int lane = tid & 31;
    const int tig = lane & 3;    // thread-in-group (col group)
    const int gid = lane >> 2;   // row group
    const int q0 = qt * BQ;

    // ---- stage Q tile (pre-scaled by 1/sqrt(256), tf32) ----
    {
        const float* src = Qg + ((size_t)b * SEQ + q0) * DH;
        for (int i = tid; i < BQ * DH / 4; i += 128) {
            int r = i >> 6;
            int c = (i & 63) << 2;
            float4 v = *(const float4*)(src + r * DH + c);
            float4 o4;
            o4.x = __uint_as_float(f2tf(v.x * 0.0625f));
            o4.y = __uint_as_float(f2tf(v.y * 0.0625f));
            o4.z = __uint_as_float(f2tf(v.z * 0.0625f));
            o4.w = __uint_as_float(f2tf(v.w * 0.0625f));
            *(float4*)&Qs[r * QS + c] = o4;
        }
    }

    float m0 = NEGINF, m1 = NEGINF;
    float l0 = 0.f, l1 = 0.f;
    float o[32][4];
    #pragma unroll
    for (int i = 0; i < 32; ++i) {
        o[i][0] = 0.f; o[i][1] = 0.f; o[i][2] = 0.f; o[i][3] = 0.f;
    }

    const int qrow0 = q0 + wid * 16 + gid;  // rows owned by accum regs {0,1}
    const int qrow1 = qrow0 + 8;            // rows owned by accum regs {2,3}

    for (int t = 0; t <= qt; ++t) {
        __syncthreads();  // previous PV / P reads done before overwriting tiles

        // ---- stage K, V tiles (tf32) + padding mask ----
        {
            const float* ks = Kg + ((size_t)b * SEQ + t * BK) * DH;
            const float* vs = Vg + ((size_t)b * SEQ + t * BK) * DH;
            #pragma unroll 2
            for (int i = tid; i < BK * DH / 4; i += 128) {
                int r = i >> 6;
                int c = (i & 63) << 2;
                float4 kv = *(const float4*)(ks + r * DH + c);
                float4 vv = *(const float4*)(vs + r * DH + c);
                float4 k4, v4;
                k4.x = __uint_as_float(f2tf(kv.x));
                k4.y = __uint_as_float(f2tf(kv.y));
                k4.z = __uint_as_float(f2tf(kv.z));
                k4.w = __uint_as_float(f2tf(kv.w));
                v4.x = __uint_as_float(f2tf(vv.x));
                v4.y = __uint_as_float(f2tf(vv.y));
                v4.z = __uint_as_float(f2tf(vv.z));
                v4.w = __uint_as_float(f2tf(vv.w));
                *(float4*)&Ks[r * QS + c] = k4;
                *(float4*)&Vs[r * QS + c] = v4;
            }
            if (tid < BK) Ms[tid] = Mg[(size_t)b * SEQ + t * BK + tid];
        }
        __syncthreads();

        // ---- S = (Q*scale) . K^T  (per warp: 16 x 64) ----
        float s[8][4];
        #pragma unroll
        for (int i = 0; i < 8; ++i) {
            s[i][0] = 0.f; s[i][1] = 0.f; s[i][2] = 0.f; s[i][3] = 0.f;
        }
        const unsigned* Qr = (const unsigned*)&Qs[(wid * 16 + gid) * QS];
        #pragma unroll
        for (int kc = 0; kc < 32; ++kc) {
            unsigned a[4];
            a[0] = Qr[kc * 8 + tig];
            a[1] = Qr[8 * QS + kc * 8 + tig];
            a[2] = Qr[kc * 8 + tig + 4];
            a[3] = Qr[8 * QS + kc * 8 + tig + 4];
            #pragma unroll
            for (int nt = 0; nt < 8; ++nt) {
                unsigned bb[2];
                const unsigned* kr = (const unsigned*)&Ks[(nt * 8 + gid) * QS + kc * 8 + tig];
                bb[0] = kr[0];
                bb[1] = kr[4];
                mma8(s[nt], a, bb);
            }
        }

        // ---- mask + online softmax ----
        const bool diag = (t == qt);
        float rmax0 = NEGINF, rmax1 = NEGINF;
        #pragma unroll
        for (int nt = 0; nt < 8; ++nt) {
            #pragma unroll
            for (int j = 0; j < 2; ++j) {
                int c = nt * 8 + 2 * tig + j;
                bool pm = (Ms[c] != 0);
                int kg = t * BK + c;
                bool v0 = pm && (!diag || kg <= qrow0);
                bool v1 = pm && (!diag || kg <= qrow1);
                if (!v0) s[nt][j] = NEGINF;
                else     rmax0 = fmaxf(rmax0, s[nt][j]);
                if (!v1) s[nt][j + 2] = NEGINF;
                else     rmax1 = fmaxf(rmax1, s[nt][j + 2]);
            }
        }
        rmax0 = fmaxf(rmax0, __shfl_xor_sync(0xffffffffu, rmax0, 1));
        rmax0 = fmaxf(rmax0, __shfl_xor_sync(0xffffffffu, rmax0, 2));
        rmax1 = fmaxf(rmax1, __shfl_xor_sync(0xffffffffu, rmax1, 1));
        rmax1 = fmaxf(rmax1, __shfl_xor_sync(0xffffffffu, rmax1, 2));

        float mn0 = fmaxf(m0, rmax0);
        float mn1 = fmaxf(m1, rmax1);
        float al0 = (mn0 == NEGINF) ? 1.f : __expf(m0 - mn0);
        float al1 = (mn1 == NEGINF) ? 1.f : __expf(m1 - mn1);

        float rs0 = 0.f, rs1 = 0.f;
        #pragma unroll
        for (int nt = 0; nt < 8; ++nt) {
            #pragma unroll
            for (int j = 0; j < 2; ++j) {
                // fmaxf(NaN/-inf, -88) clamp: masked entries -> exp(-88) ~ 6e-39 ~ 0
                float p0 = __expf(fmaxf(s[nt][j]     - mn0, -88.f));
                float p1 = __expf(fmaxf(s[nt][j + 2] - mn1, -88.f));
                s[nt][j] = p0;
                s[nt][j + 2] = p1;
                rs0 += p0;
                rs1 += p1;
            }
        }
        rs0 += __shfl_xor_sync(0xffffffffu, rs0, 1);
        rs0 += __shfl_xor_sync(0xffffffffu, rs0, 2);
        rs1 += __shfl_xor_sync(0xffffffffu, rs1, 1);
        rs1 += __shfl_xor_sync(0xffffffffu, rs1, 2);

        l0 = l0 * al0 + rs0;
        l1 = l1 * al1 + rs1;
        m0 = mn0;
        m1 = mn1;

        #pragma unroll
        for (int nt = 0; nt < 32; ++nt) {
            o[nt][0] *= al0; o[nt][1] *= al0;
            o[nt][2] *= al1; o[nt][3] *= al1;
        }

        // ---- write P to smem (tf32) for re-fragmentation ----
        {
            float* p0 = &Ps[(wid * 16 + gid) * PSS + 2 * tig];
            float* p1 = &Ps[(wid * 16 + gid + 8) * PSS + 2 * tig];
            #pragma unroll
            for (int nt = 0; nt < 8; ++nt) {
                float2 a2, b2;
                a2.x = __uint_as_float(f2tf(s[nt][0]));
                a2.y = __uint_as_float(f2tf(s[nt][1]));
                b2.x = __uint_as_float(f2tf(s[nt][2]));
                b2.y = __uint_as_float(f2tf(s[nt][3]));
                *(float2*)(p0 + nt * 8) = a2;
                *(float2*)(p1 + nt * 8) = b2;
            }
        }
        __syncthreads();

        // ---- O += P . V  (per warp: 16 x 256) ----
        unsigned pa[8][4];
        const unsigned* Pr = (const unsigned*)&Ps[(wid * 16 + gid) * PSS];
        #pragma unroll
        for (int kc = 0; kc < 8; ++kc) {
            pa[kc][0] = Pr[kc * 8 + tig];
            pa[kc][1] = Pr[8 * PSS + kc * 8 + tig];
            pa[kc][2] = Pr[kc * 8 + tig + 4];
            pa[kc][3] = Pr[8 * PSS + kc * 8 + tig + 4];
        }
        #pragma unroll
        for (int nt = 0; nt < 32; ++nt) {
            #pragma unroll
            for (int kc = 0; kc < 8; ++kc) {
                unsigned bb[2];
                bb[0] = __float_as_uint(Vs[(kc * 8 + tig)     * QS + nt * 8 + gid]);
                bb[1] = __float_as_uint(Vs[(kc * 8 + tig + 4) * QS + nt * 8 + gid]);
                mma8(o[nt], pa[kc], bb);
            }
        }
    }

    // ---- epilogue: normalize + store ----
    float i0 = (l0 > 0.f) ? (1.f / l0) : 0.f;
    float i1 = (l1 > 0.f) ? (1.f / l1) : 0.f;
    float* out = Og + ((size_t)b * SEQ + q0 + wid * 16) * DH;
    #pragma unroll
    for (int nt = 0; nt < 32; ++nt) {
        int c = nt * 8 + 2 * tig;
        float2 r0 = make_float2(o[nt][0] * i0, o[nt][1] * i0);
        float2 r1 = make_float2(o[nt][2] * i1, o[nt][3] * i1);
        *(float2*)&out[gid * DH + c] = r0;
        *(float2*)&out[(gid + 8) * DH + c] = r1;
    }
}

extern "C" void kernel_launch(void* const* d_in, const int* in_sizes, int n_in,
                              void* d_out, int out_size) {
    const float* Q = (const float*)d_in[0];
    const float* K = (const float*)d_in[1];
    const float* V = (const float*)d_in[2];
    const int*   M = (const int*)d_in[3];
    float* O = (float*)d_out;

    const size_t smem = (size_t)(3 * BQ * QS + BQ * PSS) * sizeof(float) + BK * sizeof(int);
    cudaFuncSetAttribute(attn_kernel, cudaFuncAttributeMaxDynamicSharedMemorySize, (int)smem);

    dim3 grid(SEQ / BQ, NB);
    attn_kernel<<<grid, 128, smem>>>(Q, K, V, M, O);
}

// round 2
// speedup vs baseline: 1.3461x; 1.3461x over previous
#include <cuda_runtime.h>
#include <math.h>

// Problem shape (fixed by the dataset)
#define NB   16
#define SEQ  2048
#define DH   256
#define BQ   64     // q rows per CTA
#define BK   64     // kv rows per tile
#define QS   260    // smem row stride (floats) for Q/K/V tiles
#define PSS  68     // smem row stride for P tile
#define NEGINF (-INFINITY)

__device__ __forceinline__ unsigned f2tf(float f) {
    unsigned r;
    asm("cvt.rna.tf32.f32 %0, %1;" : "=r"(r) : "f"(f));
    return r;
}

// D += A(16x8 tf32, row) * B(8x8 tf32, col)
__device__ __forceinline__ void mma8(float* d, const unsigned* a, const unsigned* b) {
    asm volatile(
        "mma.sync.aligned.m16n8k8.row.col.f32.tf32.tf32.f32 "
        "{%0,%1,%2,%3}, {%4,%5,%6,%7}, {%8,%9}, {%0,%1,%2,%3};"
        : "+f"(d[0]), "+f"(d[1]), "+f"(d[2]), "+f"(d[3])
        : "r"(a[0]), "r"(a[1]), "r"(a[2]), "r"(a[3]),
          "r"(b[0]), "r"(b[1]));
}

#define PAIR_BAR(qs) asm volatile("bar.sync %0, 64;" :: "r"((qs) + 1) : "memory")

__global__ void __launch_bounds__(256, 1) attn_kernel(
    const float* __restrict__ Qg, const float* __restrict__ Kg,
    const float* __restrict__ Vg, const int* __restrict__ Mg,
    float* __restrict__ Og)
{
    extern __shared__ float smf[];
    float* Qs = smf;                 // BQ x QS  (permuted k-chunk layout)
    float* Ks = Qs + BQ * QS;        // BK x QS  (permuted k-chunk layout)
    float* Vs = Ks + BK * QS;        // BK x QS  (natural layout)
    float* Ps = Vs + BK * QS;        // BQ x PSS (natural layout)
    float* Mx = Ps + BQ * PSS;       // [2][64] partial row max
    float* Sx = Mx + 128;            // [2][64] partial row sum
    int*   Ms = (int*)(Sx + 128);    // BK ints

    // Heavy (large qt) blocks first to pack the causal-imbalance tail.
    const int qt  = gridDim.x - 1 - blockIdx.x;
    const int b   = blockIdx.y;
    const int tid = threadIdx.x;
    const int wid = tid >> 5;
    const int lane = tid & 31;
    const int tig = lane & 3;    // thread-in-group (col group)
    const int gid = lane >> 2;   // row group
    const int qs  = wid & 3;     // q-slab (16 rows) owned by this warp (pair)
    const int hf  = wid >> 2;    // half index: QK col half / PV d half
    const int q0 = qt * BQ;

    // ---- stage Q tile (pre-scaled by 1/sqrt(256), tf32, permuted 8-col chunks) ----
    // within each 8-col chunk, store (c, c+4) adjacent: dest pair p holds orig (p, p+4)
    {
        const float* src = Qg + ((size_t)b * SEQ + q0) * DH;
        #pragma unroll
        for (int g = tid; g < BQ * DH / 8; g += 256) {
            int r  = g >> 5;
            int c8 = (g & 31) << 3;
            float4 v1 = *(const float4*)(src + r * DH + c8);
            float4 v2 = *(const float4*)(src + r * DH + c8 + 4);
            float* dst = &Qs[r * QS + c8];
            *(float2*)(dst + 0) = make_float2(__uint_as_float(f2tf(v1.x * 0.0625f)),
                                              __uint_as_float(f2tf(v2.x * 0.0625f)));
            *(float2*)(dst + 2) = make_float2(__uint_as_float(f2tf(v1.y * 0.0625f)),
                                              __uint_as_float(f2tf(v2.y * 0.0625f)));
            *(float2*)(dst + 4) = make_float2(__uint_as_float(f2tf(v1.z * 0.0625f)),
                                              __uint_as_float(f2tf(v2.z * 0.0625f)));
            *(float2*)(dst + 6) = make_float2(__uint_as_float(f2tf(v1.w * 0.0625f)),
                                              __uint_as_float(f2tf(v2.w * 0.0625f)));
        }
    }

    float m0 = NEGINF, m1 = NEGINF;
    float l0 = 0.f, l1 = 0.f;
    float o[16][4];
    #pragma unroll
    for (int i = 0; i < 16; ++i) {
        o[i][0] = 0.f; o[i][1] = 0.f; o[i][2] = 0.f; o[i][3] = 0.f;
    }

    const int qrow0 = q0 + qs * 16 + gid;  // rows owned by accum regs {0,1}
    const int qrow1 = qrow0 + 8;           // rows owned by accum regs {2,3}
    const int row0l = qs * 16 + gid;       // local row index
    const int row1l = row0l + 8;

    for (int t = 0; t <= qt; ++t) {
        __syncthreads();  // previous tile's reads done before overwriting K/V/P

        // ---- stage K (permuted), V (natural) tiles + padding mask ----
        {
            const float* ksrc = Kg + ((size_t)b * SEQ + t * BK) * DH;
            const float* vsrc = Vg + ((size_t)b * SEQ + t * BK) * DH;
            #pragma unroll
            for (int g = tid; g < BK * DH / 8; g += 256) {
                int r  = g >> 5;
                int c8 = (g & 31) << 3;
                float4 k1 = *(const float4*)(ksrc + r * DH + c8);
                float4 k2 = *(const float4*)(ksrc + r * DH + c8 + 4);
                float* kd = &Ks[r * QS + c8];
                *(float2*)(kd + 0) = make_float2(__uint_as_float(f2tf(k1.x)),
                                                 __uint_as_float(f2tf(k2.x)));
                *(float2*)(kd + 2) = make_float2(__uint_as_float(f2tf(k1.y)),
                                                 __uint_as_float(f2tf(k2.y)));
                *(float2*)(kd + 4) = make_float2(__uint_as_float(f2tf(k1.z)),
                                                 __uint_as_float(f2tf(k2.z)));
                *(float2*)(kd + 6) = make_float2(__uint_as_float(f2tf(k1.w)),
                                                 __uint_as_float(f2tf(k2.w)));
                float4 w1 = *(const float4*)(vsrc + r * DH + c8);
                float4 w2 = *(const float4*)(vsrc + r * DH + c8 + 4);
                float4 v4;
                v4.x = __uint_as_float(f2tf(w1.x));
                v4.y = __uint_as_float(f2tf(w1.y));
                v4.z = __uint_as_float(f2tf(w1.z));
                v4.w = __uint_as_float(f2tf(w1.w));
                *(float4*)&Vs[r * QS + c8] = v4;
                v4.x = __uint_as_float(f2tf(w2.x));
                v4.y = __uint_as_float(f2tf(w2.y));
                v4.z = __uint_as_float(f2tf(w2.z));
                v4.w = __uint_as_float(f2tf(w2.w));
                *(float4*)&Vs[r * QS + c8 + 4] = v4;
            }
            if (tid < BK) Ms[tid] = Mg[(size_t)b * SEQ + t * BK + tid];
        }
        __syncthreads();

        // ---- S = (Q*scale) . K^T  (per warp: 16 rows x 32 cols, half hf) ----
        float s[4][4];
        #pragma unroll
        for (int i = 0; i < 4; ++i) {
            s[i][0] = 0.f; s[i][1] = 0.f; s[i][2] = 0.f; s[i][3] = 0.f;
        }
        #pragma unroll
        for (int kc = 0; kc < 32; ++kc) {
            unsigned a[4];
            float2 lo = *(const float2*)&Qs[row0l * QS + kc * 8 + 2 * tig];
            float2 hi = *(const float2*)&Qs[row1l * QS + kc * 8 + 2 * tig];
            a[0] = __float_as_uint(lo.x);
            a[2] = __float_as_uint(lo.y);
            a[1] = __float_as_uint(hi.x);
            a[3] = __float_as_uint(hi.y);
            #pragma unroll
            for (int nt2 = 0; nt2 < 4; ++nt2) {
                int nt = hf * 4 + nt2;
                float2 kf = *(const float2*)&Ks[(nt * 8 + gid) * QS + kc * 8 + 2 * tig];
                unsigned bb[2];
                bb[0] = __float_as_uint(kf.x);
                bb[1] = __float_as_uint(kf.y);
                mma8(s[nt2], a, bb);
            }
        }

        // ---- mask + partial row max over this half ----
        const bool diag = (t == qt);
        float rmax0 = NEGINF, rmax1 = NEGINF;
        #pragma unroll
        for (int nt2 = 0; nt2 < 4; ++nt2) {
            #pragma unroll
            for (int j = 0; j < 2; ++j) {
                int c = hf * 32 + nt2 * 8 + 2 * tig + j;   // local kv col
                bool pm = (Ms[c] != 0);
                int kg = t * BK + c;
                bool v0 = pm && (!diag || kg <= qrow0);
                bool v1 = pm && (!diag || kg <= qrow1);
                if (!v0) s[nt2][j] = NEGINF;
                else     rmax0 = fmaxf(rmax0, s[nt2][j]);
                if (!v1) s[nt2][j + 2] = NEGINF;
                else     rmax1 = fmaxf(rmax1, s[nt2][j + 2]);
            }
        }
        rmax0 = fmaxf(rmax0, __shfl_xor_sync(0xffffffffu, rmax0, 1));
        rmax0 = fmaxf(rmax0, __shfl_xor_sync(0xffffffffu, rmax0, 2));
        rmax1 = fmaxf(rmax1, __shfl_xor_sync(0xffffffffu, rmax1, 1));
        rmax1 = fmaxf(rmax1, __shfl_xor_sync(0xffffffffu, rmax1, 2));

        // exchange partial max with pair partner
        if (tig == 0) {
            Mx[hf * 64 + row0l] = rmax0;
            Mx[hf * 64 + row1l] = rmax1;
        }
        PAIR_BAR(qs);
        rmax0 = fmaxf(rmax0, Mx[(1 - hf) * 64 + row0l]);
        rmax1 = fmaxf(rmax1, Mx[(1 - hf) * 64 + row1l]);

        float mn0 = fmaxf(m0, rmax0);
        float mn1 = fmaxf(m1, rmax1);
        float al0 = (mn0 == NEGINF) ? 1.f : __expf(m0 - mn0);
        float al1 = (mn1 == NEGINF) ? 1.f : __expf(m1 - mn1);

        float rs0 = 0.f, rs1 = 0.f;
        #pragma unroll
        for (int nt2 = 0; nt2 < 4; ++nt2) {
            #pragma unroll
            for (int j = 0; j < 2; ++j) {
                float p0 = __expf(fmaxf(s[nt2][j]     - mn0, -88.f));
                float p1 = __expf(fmaxf(s[nt2][j + 2] - mn1, -88.f));
                s[nt2][j] = p0;
                s[nt2][j + 2] = p1;
                rs0 += p0;
                rs1 += p1;
            }
        }
        rs0 += __shfl_xor_sync(0xffffffffu, rs0, 1);
        rs0 += __shfl_xor_sync(0xffffffffu, rs0, 2);
        rs1 += __shfl_xor_sync(0xffffffffu, rs1, 1);
        rs1 += __shfl_xor_sync(0xffffffffu, rs1, 2);

        // ---- write P half to smem (tf32, natural layout) ----
        {
            float* p0 = &Ps[row0l * PSS + hf * 32 + 2 * tig];
            float* p1 = &Ps[row1l * PSS + hf * 32 + 2 * tig];
            #pragma unroll
            for (int nt2 = 0; nt2 < 4; ++nt2) {
                float2 a2, b2;
                a2.x = __uint_as_float(f2tf(s[nt2][0]));
                a2.y = __uint_as_float(f2tf(s[nt2][1]));
                b2.x = __uint_as_float(f2tf(s[nt2][2]));
                b2.y = __uint_as_float(f2tf(s[nt2][3]));
                *(float2*)(p0 + nt2 * 8) = a2;
                *(float2*)(p1 + nt2 * 8) = b2;
            }
        }

        // exchange partial sum with pair partner
        if (tig == 0) {
            Sx[hf * 64 + row0l] = rs0;
            Sx[hf * 64 + row1l] = rs1;
        }
        PAIR_BAR(qs);
        rs0 += Sx[(1 - hf) * 64 + row0l];
        rs1 += Sx[(1 - hf) * 64 + row1l];

        l0 = l0 * al0 + rs0;
        l1 = l1 * al1 + rs1;
        m0 = mn0;
        m1 = mn1;

        #pragma unroll
        for (int nt2 = 0; nt2 < 16; ++nt2) {
            o[nt2][0] *= al0; o[nt2][1] *= al0;
            o[nt2][2] *= al1; o[nt2][3] *= al1;
        }

        // ---- O(half) += P . V(half)  (per warp: 16 rows x 128 cols) ----
        unsigned pa[8][4];
        const unsigned* Pr = (const unsigned*)&Ps[row0l * PSS];
        #pragma unroll
        for (int kc = 0; kc < 8; ++kc) {
            pa[kc][0] = Pr[kc * 8 + tig];
            pa[kc][1] = Pr[8 * PSS + kc * 8 + tig];
            pa[kc][2] = Pr[kc * 8 + tig + 4];
            pa[kc][3] = Pr[8 * PSS + kc * 8 + tig + 4];
        }
        #pragma unroll
        for (int nt2 = 0; nt2 < 16; ++nt2) {
            int colb = hf * 128 + nt2 * 8 + gid;
            #pragma unroll
            for (int kc = 0; kc < 8; ++kc) {
                unsigned bb[2];
                bb[0] = __float_as_uint(Vs[(kc * 8 + tig)     * QS + colb]);
                bb[1] = __float_as_uint(Vs[(kc * 8 + tig + 4) * QS + colb]);
                mma8(o[nt2], pa[kc], bb);
            }
        }
    }

    // ---- epilogue: normalize + store this warp's 16 x 128 half ----
    float i0 = (l0 > 0.f) ? (1.f / l0) : 0.f;
    float i1 = (l1 > 0.f) ? (1.f / l1) : 0.f;
    float* out = Og + ((size_t)b * SEQ + q0 + qs * 16) * DH + hf * 128;
    #pragma unroll
    for (int nt2 = 0; nt2 < 16; ++nt2) {
        int c = nt2 * 8 + 2 * tig;
        float2 r0 = make_float2(o[nt2][0] * i0, o[nt2][1] * i0);
        float2 r1 = make_float2(o[nt2][2] * i1, o[nt2][3] * i1);
        *(float2*)&out[gid * DH + c] = r0;
        *(float2*)&out[(gid + 8) * DH + c] = r1;
    }
}

extern "C" void kernel_launch(void* const* d_in, const int* in_sizes, int n_in,
                              void* d_out, int out_size) {
    const float* Q = (const float*)d_in[0];
    const float* K = (const float*)d_in[1];
    const float* V = (const float*)d_in[2];
    const int*   M = (const int*)d_in[3];
    float* O = (float*)d_out;

    const size_t smem = (size_t)(3 * BQ * QS + BQ * PSS + 256) * sizeof(float)
                      + BK * sizeof(int);
    cudaFuncSetAttribute(attn_kernel, cudaFuncAttributeMaxDynamicSharedMemorySize, (int)smem);

    dim3 grid(SEQ / BQ, NB);
    attn_kernel<<<grid, 256, smem>>>(Q, K, V, M, O);
}

// round 3
// speedup vs baseline: 1.3500x; 1.0029x over previous
#include <cuda_runtime.h>
#include <math.h>

// Problem shape (fixed by the dataset)
#define NB   16
#define SEQ  2048
#define DH   256
#define BQ   64     // q rows per CTA
#define BK   64     // kv rows per tile
#define QS   260    // smem row stride (floats) for Q/K/V tiles
#define PSS  68     // smem row stride for P tile
#define NEGINF (-INFINITY)

__device__ __forceinline__ unsigned f2tf(float f) {
    unsigned r;
    asm("cvt.rna.tf32.f32 %0, %1;" : "=r"(r) : "f"(f));
    return r;
}

// D += A(16x8 tf32, row) * B(8x8 tf32, col)
__device__ __forceinline__ void mma8(float* d, const unsigned* a, const unsigned* b) {
    asm volatile(
        "mma.sync.aligned.m16n8k8.row.col.f32.tf32.tf32.f32 "
        "{%0,%1,%2,%3}, {%4,%5,%6,%7}, {%8,%9}, {%0,%1,%2,%3};"
        : "+f"(d[0]), "+f"(d[1]), "+f"(d[2]), "+f"(d[3])
        : "r"(a[0]), "r"(a[1]), "r"(a[2]), "r"(a[3]),
          "r"(b[0]), "r"(b[1]));
}

#define PAIR_BAR(qs) asm volatile("bar.sync %0, 64;" :: "r"((qs) + 1) : "memory")

__global__ void __launch_bounds__(256, 1) attn_kernel(
    const float* __restrict__ Qg, const float* __restrict__ Kg,
    const float* __restrict__ Vg, const int* __restrict__ Mg,
    float* __restrict__ Og)
{
    extern __shared__ float smf[];
    float* Qs = smf;                 // BQ x QS  (permuted k-chunk layout)
    float* Ks = Qs + BQ * QS;        // BK x QS  (permuted k-chunk layout)
    float* Vs = Ks + BK * QS;        // BK x QS  (natural layout)
    float* Ps = Vs + BK * QS;        // BQ x PSS (natural layout)
    float* Mx = Ps + BQ * PSS;       // [2][64] partial row max
    float* Sx = Mx + 128;            // [2][64] partial row sum
    int*   Ms = (int*)(Sx + 128);    // BK ints

    // Heavy (large qt) blocks first to pack the causal-imbalance tail.
    const int qt  = gridDim.x - 1 - blockIdx.x;
    const int b   = blockIdx.y;
    const int tid = threadIdx.x;
    const int wid = tid >> 5;
    const int lane = tid & 31;
    const int tig = lane & 3;    // thread-in-group (col group)
    const int gid = lane >> 2;   // row group
    const int qs  = wid & 3;     // q-slab (16 rows) owned by this warp (pair)
    const int hf  = wid >> 2;    // half index: QK col half / PV d half
    const int q0 = qt * BQ;

    // ---- stage Q tile (pre-scaled by 1/sqrt(256), tf32, permuted 8-col chunks) ----
    // within each 8-col chunk, store (c, c+4) adjacent: dest pair p holds orig (p, p+4)
    {
        const float* src = Qg + ((size_t)b * SEQ + q0) * DH;
        #pragma unroll
        for (int g = tid; g < BQ * DH / 8; g += 256) {
            int r  = g >> 5;
            int c8 = (g & 31) << 3;
            float4 v1 = *(const float4*)(src + r * DH + c8);
            float4 v2 = *(const float4*)(src + r * DH + c8 + 4);
            float* dst = &Qs[r * QS + c8];
            *(float2*)(dst + 0) = make_float2(__uint_as_float(f2tf(v1.x * 0.0625f)),
                                              __uint_as_float(f2tf(v2.x * 0.0625f)));
            *(float2*)(dst + 2) = make_float2(__uint_as_float(f2tf(v1.y * 0.0625f)),
                                              __uint_as_float(f2tf(v2.y * 0.0625f)));
            *(float2*)(dst + 4) = make_float2(__uint_as_float(f2tf(v1.z * 0.0625f)),
                                              __uint_as_float(f2tf(v2.z * 0.0625f)));
            *(float2*)(dst + 6) = make_float2(__uint_as_float(f2tf(v1.w * 0.0625f)),
                                              __uint_as_float(f2tf(v2.w * 0.0625f)));
        }
    }

    float m0 = NEGINF, m1 = NEGINF;
    float l0 = 0.f, l1 = 0.f;
    float o[16][4];
    #pragma unroll
    for (int i = 0; i < 16; ++i) {
        o[i][0] = 0.f; o[i][1] = 0.f; o[i][2] = 0.f; o[i][3] = 0.f;
    }

    const int qrow0 = q0 + qs * 16 + gid;  // rows owned by accum regs {0,1}
    const int qrow1 = qrow0 + 8;           // rows owned by accum regs {2,3}
    const int row0l = qs * 16 + gid;       // local row index
    const int row1l = row0l + 8;

    for (int t = 0; t <= qt; ++t) {
        __syncthreads();  // previous tile's reads done before overwriting K/V/P

        // ---- stage K (permuted), V (natural) tiles + padding mask ----
        {
            const float* ksrc = Kg + ((size_t)b * SEQ + t * BK) * DH;
            const float* vsrc = Vg + ((size_t)b * SEQ + t * BK) * DH;
            #pragma unroll
            for (int g = tid; g < BK * DH / 8; g += 256) {
                int r  = g >> 5;
                int c8 = (g & 31) << 3;
                float4 k1 = *(const float4*)(ksrc + r * DH + c8);
                float4 k2 = *(const float4*)(ksrc + r * DH + c8 + 4);
                float* kd = &Ks[r * QS + c8];
                *(float2*)(kd + 0) = make_float2(__uint_as_float(f2tf(k1.x)),
                                                 __uint_as_float(f2tf(k2.x)));
                *(float2*)(kd + 2) = make_float2(__uint_as_float(f2tf(k1.y)),
                                                 __uint_as_float(f2tf(k2.y)));
                *(float2*)(kd + 4) = make_float2(__uint_as_float(f2tf(k1.z)),
                                                 __uint_as_float(f2tf(k2.z)));
                *(float2*)(kd + 6) = make_float2(__uint_as_float(f2tf(k1.w)),
                                                 __uint_as_float(f2tf(k2.w)));
                float4 w1 = *(const float4*)(vsrc + r * DH + c8);
                float4 w2 = *(const float4*)(vsrc + r * DH + c8 + 4);
                float4 v4;
                v4.x = __uint_as_float(f2tf(w1.x));
                v4.y = __uint_as_float(f2tf(w1.y));
                v4.z = __uint_as_float(f2tf(w1.z));
                v4.w = __uint_as_float(f2tf(w1.w));
                *(float4*)&Vs[r * QS + c8] = v4;
                v4.x = __uint_as_float(f2tf(w2.x));
                v4.y = __uint_as_float(f2tf(w2.y));
                v4.z = __uint_as_float(f2tf(w2.z));
                v4.w = __uint_as_float(f2tf(w2.w));
                *(float4*)&Vs[r * QS + c8 + 4] = v4;
            }
            if (tid < BK) Ms[tid] = Mg[(size_t)b * SEQ + t * BK + tid];
        }
        __syncthreads();

        // ---- S = (Q*scale) . K^T  (per warp: 16 rows x 32 cols, half hf) ----
        float s[4][4];
        #pragma unroll
        for (int i = 0; i < 4; ++i) {
            s[i][0] = 0.f; s[i][1] = 0.f; s[i][2] = 0.f; s[i][3] = 0.f;
        }
        #pragma unroll
        for (int kc = 0; kc < 32; ++kc) {
            unsigned a[4];
            float2 lo = *(const float2*)&Qs[row0l * QS + kc * 8 + 2 * tig];
            float2 hi = *(const float2*)&Qs[row1l * QS + kc * 8 + 2 * tig];
            a[0] = __float_as_uint(lo.x);
            a[2] = __float_as_uint(lo.y);
            a[1] = __float_as_uint(hi.x);
            a[3] = __float_as_uint(hi.y);
            #pragma unroll
            for (int nt2 = 0; nt2 < 4; ++nt2) {
                int nt = hf * 4 + nt2;
                float2 kf = *(const float2*)&Ks[(nt * 8 + gid) * QS + kc * 8 + 2 * tig];
                unsigned bb[2];
                bb[0] = __float_as_uint(kf.x);
                bb[1] = __float_as_uint(kf.y);
                mma8(s[nt2], a, bb);
            }
        }

        // ---- mask + partial row max over this half ----
        const bool diag = (t == qt);
        float rmax0 = NEGINF, rmax1 = NEGINF;
        #pragma unroll
        for (int nt2 = 0; nt2 < 4; ++nt2) {
            #pragma unroll
            for (int j = 0; j < 2; ++j) {
                int c = hf * 32 + nt2 * 8 + 2 * tig + j;   // local kv col
                bool pm = (Ms[c] != 0);
                int kg = t * BK + c;
                bool v0 = pm && (!diag || kg <= qrow0);
                bool v1 = pm && (!diag || kg <= qrow1);
                if (!v0) s[nt2][j] = NEGINF;
                else     rmax0 = fmaxf(rmax0, s[nt2][j]);
                if (!v1) s[nt2][j + 2] = NEGINF;
                else     rmax1 = fmaxf(rmax1, s[nt2][j + 2]);
            }
        }
        rmax0 = fmaxf(rmax0, __shfl_xor_sync(0xffffffffu, rmax0, 1));
        rmax0 = fmaxf(rmax0, __shfl_xor_sync(0xffffffffu, rmax0, 2));
        rmax1 = fmaxf(rmax1, __shfl_xor_sync(0xffffffffu, rmax1, 1));
        rmax1 = fmaxf(rmax1, __shfl_xor_sync(0xffffffffu, rmax1, 2));

        // exchange partial max with pair partner
        if (tig == 0) {
            Mx[hf * 64 + row0l] = rmax0;
            Mx[hf * 64 + row1l] = rmax1;
        }
        PAIR_BAR(qs);
        rmax0 = fmaxf(rmax0, Mx[(1 - hf) * 64 + row0l]);
        rmax1 = fmaxf(rmax1, Mx[(1 - hf) * 64 + row1l]);

        float mn0 = fmaxf(m0, rmax0);
        float mn1 = fmaxf(m1, rmax1);
        float al0 = (mn0 == NEGINF) ? 1.f : __expf(m0 - mn0);
        float al1 = (mn1 == NEGINF) ? 1.f : __expf(m1 - mn1);

        float rs0 = 0.f, rs1 = 0.f;
        #pragma unroll
        for (int nt2 = 0; nt2 < 4; ++nt2) {
            #pragma unroll
            for (int j = 0; j < 2; ++j) {
                float p0 = __expf(fmaxf(s[nt2][j]     - mn0, -88.f));
                float p1 = __expf(fmaxf(s[nt2][j + 2] - mn1, -88.f));
                s[nt2][j] = p0;
                s[nt2][j + 2] = p1;
                rs0 += p0;
                rs1 += p1;
            }
        }
        rs0 += __shfl_xor_sync(0xffffffffu, rs0, 1);
        rs0 += __shfl_xor_sync(0xffffffffu, rs0, 2);
        rs1 += __shfl_xor_sync(0xffffffffu, rs1, 1);
        rs1 += __shfl_xor_sync(0xffffffffu, rs1, 2);

        // ---- write P half to smem (tf32, natural layout) ----
        {
            float* p0 = &Ps[row0l * PSS + hf * 32 + 2 * tig];
            float* p1 = &Ps[row1l * PSS + hf * 32 + 2 * tig];
            #pragma unroll
            for (int nt2 = 0; nt2 < 4; ++nt2) {
                float2 a2, b2;
                a2.x = __uint_as_float(f2tf(s[nt2][0]));
                a2.y = __uint_as_float(f2tf(s[nt2][1]));
                b2.x = __uint_as_float(f2tf(s[nt2][2]));
                b2.y = __uint_as_float(f2tf(s[nt2][3]));
                *(float2*)(p0 + nt2 * 8) = a2;
                *(float2*)(p1 + nt2 * 8) = b2;
            }
        }

        // exchange partial sum with pair partner
        if (tig == 0) {
            Sx[hf * 64 + row0l] = rs0;
            Sx[hf * 64 + row1l] = rs1;
        }
        PAIR_BAR(qs);
        rs0 += Sx[(1 - hf) * 64 + row0l];
        rs1 += Sx[(1 - hf) * 64 + row1l];

        l0 = l0 * al0 + rs0;
        l1 = l1 * al1 + rs1;
        m0 = mn0;
        m1 = mn1;

        #pragma unroll
        for (int nt2 = 0; nt2 < 16; ++nt2) {
            o[nt2][0] *= al0; o[nt2][1] *= al0;
            o[nt2][2] *= al1; o[nt2][3] *= al1;
        }

        // ---- O(half) += P . V(half)  (per warp: 16 rows x 128 cols) ----
        unsigned pa[8][4];
        const unsigned* Pr = (const unsigned*)&Ps[row0l * PSS];
        #pragma unroll
        for (int kc = 0; kc < 8; ++kc) {
            pa[kc][0] = Pr[kc * 8 + tig];
            pa[kc][1] = Pr[8 * PSS + kc * 8 + tig];
            pa[kc][2] = Pr[kc * 8 + tig + 4];
            pa[kc][3] = Pr[8 * PSS + kc * 8 + tig + 4];
        }
        #pragma unroll
        for (int nt2 = 0; nt2 < 16; ++nt2) {
            int colb = hf * 128 + nt2 * 8 + gid;
            #pragma unroll
            for (int kc = 0; kc < 8; ++kc) {
                unsigned bb[2];
                bb[0] = __float_as_uint(Vs[(kc * 8 + tig)     * QS + colb]);
                bb[1] = __float_as_uint(Vs[(kc * 8 + tig + 4) * QS + colb]);
                mma8(o[nt2], pa[kc], bb);
            }
        }
    }

    // ---- epilogue: normalize + store this warp's 16 x 128 half ----
    float i0 = (l0 > 0.f) ? (1.f / l0) : 0.f;
    float i1 = (l1 > 0.f) ? (1.f / l1) : 0.f;
    float* out = Og + ((size_t)b * SEQ + q0 + qs * 16) * DH + hf * 128;
    #pragma unroll
    for (int nt2 = 0; nt2 < 16; ++nt2) {
        int c = nt2 * 8 + 2 * tig;
        float2 r0 = make_float2(o[nt2][0] * i0, o[nt2][1] * i0);
        float2 r1 = make_float2(o[nt2][2] * i1, o[nt2][3] * i1);
        *(float2*)&out[gid * DH + c] = r0;
        *(float2*)&out[(gid + 8) * DH + c] = r1;
    }
}

extern "C" void kernel_launch(void* const* d_in, const int* in_sizes, int n_in,
                              void* d_out, int out_size) {
    const float* Q = (const float*)d_in[0];
    const float* K = (const float*)d_in[1];
    const float* V = (const float*)d_in[2];
    const int*   M = (const int*)d_in[3];
    float* O = (float*)d_out;

    const size_t smem = (size_t)(3 * BQ * QS + BQ * PSS + 256) * sizeof(float)
                      + BK * sizeof(int);
    cudaFuncSetAttribute(attn_kernel, cudaFuncAttributeMaxDynamicSharedMemorySize, (int)smem);

    dim3 grid(SEQ / BQ, NB);
    attn_kernel<<<grid, 256, smem>>>(Q, K, V, M, O);
}

// round 6
// speedup vs baseline: 2.3865x; 1.7678x over previous
#include <cuda_runtime.h>
#include <cuda_fp16.h>
#include <math.h>
#include <stdint.h>

#define SEQ 2048
#define DH  256
#define NEGINF (-INFINITY)
#define STRQ 528   // Q/K/V smem row stride bytes (264 halves, odd*16B)
#define STRP 144   // P smem row stride bytes (72 halves)
#define OFF_Q  0
#define OFF_K  33792
#define OFF_V  67584
#define OFF_P  101376
#define OFF_MX 110592
#define OFF_SX 111104
#define OFF_MS 111616
#define SM_TOTAL 111872

__device__ __forceinline__ uint32_t smem_u32(const void* p) {
    uint32_t a;
    asm("{ .reg .u64 t; cvta.to.shared.u64 t, %1; cvt.u32.u64 %0, t; }" : "=r"(a) : "l"(p));
    return a;
}
__device__ __forceinline__ uint32_t pack2(float a, float b) {
    __half2 h = __floats2half2_rn(a, b);
    return *reinterpret_cast<uint32_t*>(&h);
}
__device__ __forceinline__ void ldsm4(uint32_t* r, uint32_t a) {
    asm volatile("ldmatrix.sync.aligned.m8n8.x4.shared.b16 {%0,%1,%2,%3}, [%4];"
        : "=r"(r[0]), "=r"(r[1]), "=r"(r[2]), "=r"(r[3]) : "r"(a));
}
__device__ __forceinline__ void ldsm4t(uint32_t* r, uint32_t a) {
    asm volatile("ldmatrix.sync.aligned.m8n8.x4.trans.shared.b16 {%0,%1,%2,%3}, [%4];"
        : "=r"(r[0]), "=r"(r[1]), "=r"(r[2]), "=r"(r[3]) : "r"(a));
}
__device__ __forceinline__ void mma16(float* d, const uint32_t* a, const uint32_t* b) {
    asm volatile(
        "mma.sync.aligned.m16n8k16.row.col.f32.f16.f16.f32 "
        "{%0,%1,%2,%3}, {%4,%5,%6,%7}, {%8,%9}, {%0,%1,%2,%3};"
        : "+f"(d[0]), "+f"(d[1]), "+f"(d[2]), "+f"(d[3])
        : "r"(a[0]), "r"(a[1]), "r"(a[2]), "r"(a[3]), "r"(b[0]), "r"(b[1]));
}
#define PAIR_BAR(qs) asm volatile("bar.sync %0, 64;" :: "r"((qs) + 1) : "memory")

// fp32 [64 x 256] gmem -> fp16 smem rows of STRQ bytes
__device__ __forceinline__ void stage(const float* __restrict__ src, char* dst,
                                      int tid, float sc) {
    for (int gi = tid; gi < 2048; gi += 256) {
        int r = gi >> 5, c8 = (gi & 31) << 3;
        const float* p = src + (size_t)r * DH + c8;
        float4 x = *(const float4*)p;
        float4 y = *(const float4*)(p + 4);
        uint4 w = make_uint4(pack2(x.x * sc, x.y * sc), pack2(x.z * sc, x.w * sc),
                             pack2(y.x * sc, y.y * sc), pack2(y.z * sc, y.w * sc));
        *(uint4*)(dst + r * STRQ + c8 * 2) = w;
    }
}

__global__ void __launch_bounds__(256, 1) attn_kernel(
    const float* __restrict__ Qg, const float* __restrict__ Kg,
    const float* __restrict__ Vg, const int* __restrict__ Mg,
    float* __restrict__ Og)
{
    extern __shared__ char sm[];
    const uint32_t smb = smem_u32(sm);
    const int tid = threadIdx.x, wid = tid >> 5, lane = tid & 31;
    const int tig = lane & 3, gid = lane >> 2;
    const int qs = wid & 3, hf = wid >> 2;

    const int lane7 = lane & 7;
    const int rAl = lane7 + ((lane >> 3) & 1) * 8;        // A-frag row (local 0-15)
    const int kA  = (lane >> 4) * 8;                      // A-frag k offset
    const int rB  = lane7 + (lane >> 4) * 8;              // B-frag n offset (0-15)
    const int kB  = ((lane >> 3) & 1) * 8;                // B-frag k offset

    const uint32_t aQ = smb + OFF_Q + (qs * 16 + rAl) * STRQ + kA * 2;
    const uint32_t bK = smb + OFF_K + (hf * 32 + rB) * STRQ + kB * 2;
    const uint32_t aP = smb + OFF_P + (qs * 16 + rAl) * STRP + kA * 2;
    const uint32_t bV = smb + OFF_V + rAl * STRQ + (hf * 128 + (lane >> 4) * 8) * 2;
    float* const Mx = (float*)(sm + OFF_MX);
    float* const Sx = (float*)(sm + OFF_SX);
    int* const Ms = (int*)(sm + OFF_MS);

    const int qt = 31 - (int)blockIdx.x;
    const int b  = (int)blockIdx.y;
    const int q0 = qt * 64;

    stage(Qg + ((size_t)b * SEQ + q0) * DH, sm + OFF_Q, tid, 0.0625f);

    float m0 = NEGINF, m1 = NEGINF, l0 = 0.f, l1 = 0.f;
    float o[16][4];
    #pragma unroll
    for (int i = 0; i < 16; ++i) {
        o[i][0] = 0.f; o[i][1] = 0.f; o[i][2] = 0.f; o[i][3] = 0.f;
    }
    const int qrow0 = q0 + qs * 16 + gid;
    const int qrow1 = qrow0 + 8;
    const int row0l = qs * 16 + gid, row1l = row0l + 8;

    #pragma unroll 1
    for (int t = 0; t <= qt; ++t) {
        __syncthreads();
        stage(Kg + ((size_t)b * SEQ + t * 64) * DH, sm + OFF_K, tid, 1.f);
        stage(Vg + ((size_t)b * SEQ + t * 64) * DH, sm + OFF_V, tid, 1.f);
        if (tid < 64) Ms[tid] = Mg[(size_t)b * SEQ + t * 64 + tid];
        __syncthreads();

        // ---- S = Q.K^T : per warp 16 rows x 32 cols ----
        float s[4][4];
        #pragma unroll
        for (int i = 0; i < 4; ++i) {
            s[i][0] = 0.f; s[i][1] = 0.f; s[i][2] = 0.f; s[i][3] = 0.f;
        }
        #pragma unroll
        for (int ks = 0; ks < 16; ++ks) {
            uint32_t a[4];
            ldsm4(a, aQ + ks * 32);
            #pragma unroll
            for (int np = 0; np < 2; ++np) {
                uint32_t bb[4];
                ldsm4(bb, bK + np * 16 * STRQ + ks * 32);
                mma16(s[np * 2], a, bb);
                mma16(s[np * 2 + 1], a, bb + 2);
            }
        }

        // ---- mask + softmax (cols hf*32 + nf*8 + 2*tig + j) ----
        const bool diag = (t == qt);
        float rmax0 = NEGINF, rmax1 = NEGINF;
        #pragma unroll
        for (int nf = 0; nf < 4; ++nf) {
            #pragma unroll
            for (int j = 0; j < 2; ++j) {
                int c = hf * 32 + nf * 8 + 2 * tig + j;
                bool pm = (Ms[c] != 0);
                int kg = t * 64 + c;
                bool v0 = pm && (!diag || kg <= qrow0);
                bool v1 = pm && (!diag || kg <= qrow1);
                if (!v0) s[nf][j] = NEGINF; else rmax0 = fmaxf(rmax0, s[nf][j]);
                if (!v1) s[nf][j + 2] = NEGINF; else rmax1 = fmaxf(rmax1, s[nf][j + 2]);
            }
        }
        rmax0 = fmaxf(rmax0, __shfl_xor_sync(~0u, rmax0, 1));
        rmax0 = fmaxf(rmax0, __shfl_xor_sync(~0u, rmax0, 2));
        rmax1 = fmaxf(rmax1, __shfl_xor_sync(~0u, rmax1, 1));
        rmax1 = fmaxf(rmax1, __shfl_xor_sync(~0u, rmax1, 2));
        if (tig == 0) { Mx[hf * 64 + row0l] = rmax0; Mx[hf * 64 + row1l] = rmax1; }
        PAIR_BAR(qs);
        rmax0 = fmaxf(rmax0, Mx[(1 - hf) * 64 + row0l]);
        rmax1 = fmaxf(rmax1, Mx[(1 - hf) * 64 + row1l]);

        float mn0 = fmaxf(m0, rmax0), mn1 = fmaxf(m1, rmax1);
        float al0 = (mn0 == NEGINF) ? 1.f : __expf(m0 - mn0);
        float al1 = (mn1 == NEGINF) ? 1.f : __expf(m1 - mn1);

        float rs0 = 0.f, rs1 = 0.f;
        uint32_t pk[4][2];
        #pragma unroll
        for (int nf = 0; nf < 4; ++nf) {
            float p0 = __expf(fmaxf(s[nf][0] - mn0, -88.f));
            float p1 = __expf(fmaxf(s[nf][1] - mn0, -88.f));
            float p2 = __expf(fmaxf(s[nf][2] - mn1, -88.f));
            float p3 = __expf(fmaxf(s[nf][3] - mn1, -88.f));
            rs0 += p0 + p1; rs1 += p2 + p3;
            pk[nf][0] = pack2(p0, p1);
            pk[nf][1] = pack2(p2, p3);
        }
        rs0 += __shfl_xor_sync(~0u, rs0, 1);
        rs0 += __shfl_xor_sync(~0u, rs0, 2);
        rs1 += __shfl_xor_sync(~0u, rs1, 1);
        rs1 += __shfl_xor_sync(~0u, rs1, 2);

        // P halves -> smem (fp16)
        {
            char* p0 = sm + OFF_P + row0l * STRP + (hf * 32 + 2 * tig) * 2;
            char* p1 = sm + OFF_P + row1l * STRP + (hf * 32 + 2 * tig) * 2;
            #pragma unroll
            for (int nf = 0; nf < 4; ++nf) {
                *(uint32_t*)(p0 + nf * 16) = pk[nf][0];
                *(uint32_t*)(p1 + nf * 16) = pk[nf][1];
            }
        }
        if (tig == 0) { Sx[hf * 64 + row0l] = rs0; Sx[hf * 64 + row1l] = rs1; }
        PAIR_BAR(qs);
        rs0 += Sx[(1 - hf) * 64 + row0l];
        rs1 += Sx[(1 - hf) * 64 + row1l];
        l0 = l0 * al0 + rs0; l1 = l1 * al1 + rs1;
        m0 = mn0; m1 = mn1;
        #pragma unroll
        for (int nf = 0; nf < 16; ++nf) {
            o[nf][0] *= al0; o[nf][1] *= al0;
            o[nf][2] *= al1; o[nf][3] *= al1;
        }

        // ---- O(half) += P.V : per warp 16 rows x 128 cols ----
        #pragma unroll
        for (int ks = 0; ks < 4; ++ks) {
            uint32_t pa[4];
            ldsm4(pa, aP + ks * 32);
            #pragma unroll
            for (int dp = 0; dp < 8; ++dp) {
                uint32_t bb[4];
                ldsm4t(bb, bV + ks * 16 * STRQ + dp * 32);
                mma16(o[dp * 2], pa, bb);
                mma16(o[dp * 2 + 1], pa, bb + 2);
            }
        }
    }

    // ---- epilogue ----
    float i0 = (l0 > 0.f) ? (1.f / l0) : 0.f;
    float i1 = (l1 > 0.f) ? (1.f / l1) : 0.f;
    float* out = Og + ((size_t)b * SEQ + q0 + qs * 16) * DH + hf * 128;
    #pragma unroll
    for (int nf = 0; nf < 16; ++nf) {
        int c = nf * 8 + 2 * tig;
        *(float2*)&out[gid * DH + c] = make_float2(o[nf][0] * i0, o[nf][1] * i0);
        *(float2*)&out[(gid + 8) * DH + c] = make_float2(o[nf][2] * i1, o[nf][3] * i1);
    }
}

extern "C" void kernel_launch(void* const* d_in, const int* in_sizes, int n_in,
                              void* d_out, int out_size) {
    (void)in_sizes; (void)n_in; (void)out_size;
    cudaFuncSetAttribute(attn_kernel, cudaFuncAttributeMaxDynamicSharedMemorySize, SM_TOTAL);
    dim3 grid(32, 16);
    attn_kernel<<<grid, 256, SM_TOTAL>>>((const float*)d_in[0], (const float*)d_in[1],
                                         (const float*)d_in[2], (const int*)d_in[3],
                                         (float*)d_out);
}

// round 7
// speedup vs baseline: 3.7167x; 1.5574x over previous
#include <cuda_runtime.h>
#include <cuda_fp16.h>
#include <math.h>
#include <stdint.h>

#define SEQ 2048
#define DH  256
#define NEGINF (-INFINITY)
#define STRQ 528
#define STRP 144
#define OFF_Q  0
#define OFF_K0 33792
#define OFF_K1 67584
#define OFF_V0 101376
#define OFF_V1 135168
#define OFF_P  168960
#define OFF_MX 178176
#define OFF_SX 178688
#define OFF_MS 179200
#define SM_TOTAL 179712
#define KVSTEP 33792

__device__ __half Qh_g[16u * 2048u * 256u];
__device__ __half Kh_g[16u * 2048u * 256u];
__device__ __half Vh_g[16u * 2048u * 256u];

__device__ __forceinline__ uint32_t smem_u32(const void* p) {
    uint32_t a;
    asm("{ .reg .u64 t; cvta.to.shared.u64 t, %1; cvt.u32.u64 %0, t; }" : "=r"(a) : "l"(p));
    return a;
}
__device__ __forceinline__ uint32_t pack2(float a, float b) {
    __half2 h = __floats2half2_rn(a, b);
    return *reinterpret_cast<uint32_t*>(&h);
}
__device__ __forceinline__ void ldsm4(uint32_t* r, uint32_t a) {
    asm volatile("ldmatrix.sync.aligned.m8n8.x4.shared.b16 {%0,%1,%2,%3}, [%4];"
        : "=r"(r[0]), "=r"(r[1]), "=r"(r[2]), "=r"(r[3]) : "r"(a));
}
__device__ __forceinline__ void ldsm4t(uint32_t* r, uint32_t a) {
    asm volatile("ldmatrix.sync.aligned.m8n8.x4.trans.shared.b16 {%0,%1,%2,%3}, [%4];"
        : "=r"(r[0]), "=r"(r[1]), "=r"(r[2]), "=r"(r[3]) : "r"(a));
}
__device__ __forceinline__ void mma16(float* d, const uint32_t* a, const uint32_t* b) {
    asm volatile(
        "mma.sync.aligned.m16n8k16.row.col.f32.f16.f16.f32 "
        "{%0,%1,%2,%3}, {%4,%5,%6,%7}, {%8,%9}, {%0,%1,%2,%3};"
        : "+f"(d[0]), "+f"(d[1]), "+f"(d[2]), "+f"(d[3])
        : "r"(a[0]), "r"(a[1]), "r"(a[2]), "r"(a[3]), "r"(b[0]), "r"(b[1]));
}
#define PAIR_BAR(qs) asm volatile("bar.sync %0, 64;" :: "r"((qs) + 1) : "memory")
#define CP16(d, s)   asm volatile("cp.async.cg.shared.global [%0], [%1], 16;" :: "r"(d), "l"(s))
#define CP_COMMIT()  asm volatile("cp.async.commit_group;" ::: "memory")
#define CP_WAIT(n)   asm volatile("cp.async.wait_group %0;" :: "n"(n) : "memory")

// ---- prepass: fp32 -> fp16 (Q scaled by 1/16) ----
__global__ void cvt_kernel(const float* __restrict__ Q, const float* __restrict__ K,
                           const float* __restrict__ V) {
    size_t i = ((size_t)blockIdx.x * 256 + threadIdx.x) * 8;
    int w = blockIdx.y;
    const float* s = (w == 0) ? Q : (w == 1) ? K : V;
    __half* d = (w == 0) ? Qh_g : (w == 1) ? Kh_g : Vh_g;
    float sc = (w == 0) ? 0.0625f : 1.f;
    float4 a = *(const float4*)(s + i);
    float4 b = *(const float4*)(s + i + 4);
    uint4 u = make_uint4(pack2(a.x * sc, a.y * sc), pack2(a.z * sc, a.w * sc),
                         pack2(b.x * sc, b.y * sc), pack2(b.z * sc, b.w * sc));
    *(uint4*)(d + i) = u;
}

__device__ __forceinline__ void issue_kv(size_t base, uint32_t kdst, uint32_t vdst, int tid) {
    #pragma unroll
    for (int gi = tid; gi < 2048; gi += 256) {
        int r = gi >> 5, c = gi & 31;
        uint32_t off = r * STRQ + c * 16;
        CP16(kdst + off, Kh_g + base + r * 256 + c * 8);
        CP16(vdst + off, Vh_g + base + r * 256 + c * 8);
    }
}

__global__ void __launch_bounds__(256, 1) attn_kernel(
    const int* __restrict__ Mg, float* __restrict__ Og)
{
    extern __shared__ char sm[];
    const uint32_t smb = smem_u32(sm);
    const int tid = threadIdx.x, wid = tid >> 5, lane = tid & 31;
    const int tig = lane & 3, gid = lane >> 2;
    const int qs = wid & 3, hf = wid >> 2;
    const int lane7 = lane & 7;
    const int rAl = lane7 + ((lane >> 3) & 1) * 8;
    const int kA  = (lane >> 4) * 8;
    const int rB  = lane7 + (lane >> 4) * 8;
    const int kB  = ((lane >> 3) & 1) * 8;

    const uint32_t aQ  = smb + OFF_Q + (qs * 16 + rAl) * STRQ + kA * 2;
    const uint32_t bK0 = smb + OFF_K0 + (hf * 32 + rB) * STRQ + kB * 2;
    const uint32_t aP  = smb + OFF_P + (qs * 16 + rAl) * STRP + kA * 2;
    const uint32_t bV0 = smb + OFF_V0 + rAl * STRQ + (hf * 128 + (lane >> 4) * 8) * 2;
    float* const Mx = (float*)(sm + OFF_MX);
    float* const Sx = (float*)(sm + OFF_SX);

    const int qt = 31 - (int)blockIdx.x;
    const int b  = (int)blockIdx.y;
    const int q0 = qt * 64;
    const size_t bseq = (size_t)b * SEQ * DH;

    // prologue: Q + tile0 K/V + mask0, one cp.async group
    #pragma unroll
    for (int gi = tid; gi < 2048; gi += 256) {
        int r = gi >> 5, c = gi & 31;
        CP16(smb + OFF_Q + r * STRQ + c * 16, Qh_g + bseq + (size_t)(q0 + r) * 256 + c * 8);
    }
    issue_kv(bseq, smb + OFF_K0, smb + OFF_V0, tid);
    if (tid < 16) CP16(smb + OFF_MS + tid * 16, Mg + (size_t)b * SEQ + tid * 4);
    CP_COMMIT();

    float m0 = NEGINF, m1 = NEGINF, l0 = 0.f, l1 = 0.f;
    float o[16][4];
    #pragma unroll
    for (int i = 0; i < 16; ++i) {
        o[i][0] = 0.f; o[i][1] = 0.f; o[i][2] = 0.f; o[i][3] = 0.f;
    }
    const int qrow0 = q0 + qs * 16 + gid;
    const int qrow1 = qrow0 + 8;
    const int row0l = qs * 16 + gid, row1l = row0l + 8;

    #pragma unroll 1
    for (int t = 0; t <= qt; ++t) {
        const uint32_t bufo = (uint32_t)(t & 1) * KVSTEP;
        if (t < qt) {
            const uint32_t nbuf = (uint32_t)((t + 1) & 1) * KVSTEP;
            issue_kv(bseq + (size_t)(t + 1) * 64 * 256, smb + OFF_K0 + nbuf, smb + OFF_V0 + nbuf, tid);
            if (tid < 16)
                CP16(smb + OFF_MS + ((t + 1) & 1) * 256 + tid * 16,
                     Mg + (size_t)b * SEQ + (t + 1) * 64 + tid * 4);
            CP_COMMIT();
            CP_WAIT(1);
        } else {
            CP_WAIT(0);
        }
        __syncthreads();

        const int* Ms = (const int*)(sm + OFF_MS + (t & 1) * 256);
        // ---- S = Q.K^T ----
        float s[4][4];
        #pragma unroll
        for (int i = 0; i < 4; ++i) {
            s[i][0] = 0.f; s[i][1] = 0.f; s[i][2] = 0.f; s[i][3] = 0.f;
        }
        #pragma unroll
        for (int ks = 0; ks < 16; ++ks) {
            uint32_t a[4];
            ldsm4(a, aQ + ks * 32);
            #pragma unroll
            for (int np = 0; np < 2; ++np) {
                uint32_t bb[4];
                ldsm4(bb, bK0 + bufo + np * 16 * STRQ + ks * 32);
                mma16(s[np * 2], a, bb);
                mma16(s[np * 2 + 1], a, bb + 2);
            }
        }

        // ---- mask + online softmax ----
        const bool diag = (t == qt);
        float rmax0 = NEGINF, rmax1 = NEGINF;
        #pragma unroll
        for (int nf = 0; nf < 4; ++nf) {
            #pragma unroll
            for (int j = 0; j < 2; ++j) {
                int c = hf * 32 + nf * 8 + 2 * tig + j;
                bool pm = (Ms[c] != 0);
                int kg = t * 64 + c;
                bool v0 = pm && (!diag || kg <= qrow0);
                bool v1 = pm && (!diag || kg <= qrow1);
                if (!v0) s[nf][j] = NEGINF; else rmax0 = fmaxf(rmax0, s[nf][j]);
                if (!v1) s[nf][j + 2] = NEGINF; else rmax1 = fmaxf(rmax1, s[nf][j + 2]);
            }
        }
        rmax0 = fmaxf(rmax0, __shfl_xor_sync(~0u, rmax0, 1));
        rmax0 = fmaxf(rmax0, __shfl_xor_sync(~0u, rmax0, 2));
        rmax1 = fmaxf(rmax1, __shfl_xor_sync(~0u, rmax1, 1));
        rmax1 = fmaxf(rmax1, __shfl_xor_sync(~0u, rmax1, 2));
        if (tig == 0) { Mx[hf * 64 + row0l] = rmax0; Mx[hf * 64 + row1l] = rmax1; }
        PAIR_BAR(qs);
        rmax0 = fmaxf(rmax0, Mx[(1 - hf) * 64 + row0l]);
        rmax1 = fmaxf(rmax1, Mx[(1 - hf) * 64 + row1l]);

        float mn0 = fmaxf(m0, rmax0), mn1 = fmaxf(m1, rmax1);
        float al0 = (mn0 == NEGINF) ? 1.f : __expf(m0 - mn0);
        float al1 = (mn1 == NEGINF) ? 1.f : __expf(m1 - mn1);

        float rs0 = 0.f, rs1 = 0.f;
        uint32_t pk[4][2];
        #pragma unroll
        for (int nf = 0; nf < 4; ++nf) {
            float p0 = __expf(fmaxf(s[nf][0] - mn0, -88.f));
            float p1 = __expf(fmaxf(s[nf][1] - mn0, -88.f));
            float p2 = __expf(fmaxf(s[nf][2] - mn1, -88.f));
            float p3 = __expf(fmaxf(s[nf][3] - mn1, -88.f));
            rs0 += p0 + p1; rs1 += p2 + p3;
            pk[nf][0] = pack2(p0, p1);
            pk[nf][1] = pack2(p2, p3);
        }
        rs0 += __shfl_xor_sync(~0u, rs0, 1);
        rs0 += __shfl_xor_sync(~0u, rs0, 2);
        rs1 += __shfl_xor_sync(~0u, rs1, 1);
        rs1 += __shfl_xor_sync(~0u, rs1, 2);

        {
            char* p0 = sm + OFF_P + row0l * STRP + (hf * 32 + 2 * tig) * 2;
            char* p1 = sm + OFF_P + row1l * STRP + (hf * 32 + 2 * tig) * 2;
            #pragma unroll
            for (int nf = 0; nf < 4; ++nf) {
                *(uint32_t*)(p0 + nf * 16) = pk[nf][0];
                *(uint32_t*)(p1 + nf * 16) = pk[nf][1];
            }
        }
        if (tig == 0) { Sx[hf * 64 + row0l] = rs0; Sx[hf * 64 + row1l] = rs1; }
        PAIR_BAR(qs);
        rs0 += Sx[(1 - hf) * 64 + row0l];
        rs1 += Sx[(1 - hf) * 64 + row1l];
        l0 = l0 * al0 + rs0; l1 = l1 * al1 + rs1;
        m0 = mn0; m1 = mn1;
        #pragma unroll
        for (int nf = 0; nf < 16; ++nf) {
            o[nf][0] *= al0; o[nf][1] *= al0;
            o[nf][2] *= al1; o[nf][3] *= al1;
        }

        // ---- O += P.V ----
        #pragma unroll
        for (int ks = 0; ks < 4; ++ks) {
            uint32_t pa[4];
            ldsm4(pa, aP + ks * 32);
            #pragma unroll
            for (int dp = 0; dp < 8; ++dp) {
                uint32_t bb[4];
                ldsm4t(bb, bV0 + bufo + ks * 16 * STRQ + dp * 32);
                mma16(o[dp * 2], pa, bb);
                mma16(o[dp * 2 + 1], pa, bb + 2);
            }
        }
        __syncthreads();
    }

    float i0 = (l0 > 0.f) ? (1.f / l0) : 0.f;
    float i1 = (l1 > 0.f) ? (1.f / l1) : 0.f;
    float* out = Og + ((size_t)b * SEQ + q0 + qs * 16) * DH + hf * 128;
    #pragma unroll
    for (int nf = 0; nf < 16; ++nf) {
        int c = nf * 8 + 2 * tig;
        *(float2*)&out[gid * DH + c] = make_float2(o[nf][0] * i0, o[nf][1] * i0);
        *(float2*)&out[(gid + 8) * DH + c] = make_float2(o[nf][2] * i1, o[nf][3] * i1);
    }
}

extern "C" void kernel_launch(void* const* d_in, const int* in_sizes, int n_in,
                              void* d_out, int out_size) {
    (void)in_sizes; (void)n_in; (void)out_size;
    cvt_kernel<<<dim3(4096, 3), 256>>>((const float*)d_in[0], (const float*)d_in[1],
                                       (const float*)d_in[2]);
    cudaFuncSetAttribute(attn_kernel, cudaFuncAttributeMaxDynamicSharedMemorySize, SM_TOTAL);
    dim3 grid(32, 16);
    attn_kernel<<<grid, 256, SM_TOTAL>>>((const int*)d_in[3], (float*)d_out);
}